// round 6
// baseline (speedup 1.0000x reference)
#include <cuda_runtime.h>
#include <cuda_fp16.h>
#include <cstdint>

// ============================================================================
// out[b,l,d] = sum_{i,j} x0[b,i,d]*x1[b,j,d]*filters[i*64+j, l]
// B=2048, F1=F2=64, D=16, L=16.
//
// GEMM view: z[m,(i,l)] = sum_j x1[m,j] * W[(i,l),j], m=(b,d), then
// out[m,l] = sum_i x0[m,i] * z[m,(i,l)] in an fp32 register epilogue.
// mma.sync.m16n8k16, W as A operand (16 l-rows of one i), x1 as B operand.
// R6: two i's per B-pass (halves SMEM traffic, 2x chain ILP) + depth-2
// accumulation chains (4x total HMMA ILP).
// ============================================================================

// Pre-arranged W fragment image: [i(64)][kstep(4)][lane(32)] x 16B.
__device__ __align__(16) uint4 g_Wfrag[64 * 4 * 32];

__device__ __forceinline__ uint32_t pack_half2(float a, float b) {
    __half2 h = __floats2half2_rn(a, b);   // .x (low 16b) = a, .y = b
    return *(uint32_t*)&h;
}

__device__ __forceinline__ void mma16816(float c[4], const uint4& a, const uint2& b) {
    asm volatile(
        "mma.sync.aligned.m16n8k16.row.col.f32.f16.f16.f32 "
        "{%0,%1,%2,%3}, {%4,%5,%6,%7}, {%8,%9}, {%0,%1,%2,%3};\n"
        : "+f"(c[0]), "+f"(c[1]), "+f"(c[2]), "+f"(c[3])
        : "r"(a.x), "r"(a.y), "r"(a.z), "r"(a.w), "r"(b.x), "r"(b.y));
}

// ---------------------------------------------------------- prep kernel -----
// A-fragment mapping (m16k16, row-major), lane = 4*gid + q:
//   reg0 = {A[gid][2q],   A[gid][2q+1]}    reg1 = {A[gid+8][2q],   A[gid+8][2q+1]}
//   reg2 = {A[gid][2q+8], A[gid][2q+9]}    reg3 = {A[gid+8][2q+8], A[gid+8][2q+9]}
// A row = l; A col = k = j (global j = 16*kstep + local).
__global__ void prep_w_kernel(const float* __restrict__ filters) {
    int idx  = blockIdx.x * 256 + threadIdx.x;    // 8192 total
    int i    = (idx >> 7) & 63;
    int t    = (idx >> 5) & 3;
    int lane = idx & 31;
    int gid = lane >> 2, q = lane & 3;
    int k0 = t * 16 + q * 2;
    int l0 = gid, l1 = gid + 8;

    float e[8];
    int ls[8] = {l0, l0, l1, l1, l0, l0, l1, l1};
    int ks[8] = {k0, k0 + 1, k0, k0 + 1, k0 + 8, k0 + 9, k0 + 8, k0 + 9};
    #pragma unroll
    for (int j = 0; j < 8; ++j)
        e[j] = filters[(i * 64 + ks[j]) * 16 + ls[j]];

    g_Wfrag[idx] = make_uint4(pack_half2(e[0], e[1]), pack_half2(e[2], e[3]),
                              pack_half2(e[4], e[5]), pack_half2(e[6], e[7]));
}

// ------------------------------------------------------------ main kernel ---
// SMEM: x1B (16KB) | x0e (32KB) | wb chunk buffers (36KB; staging overlay)
static constexpr int SM_X1B  = 0;        // 2048 x uint2  (B fragments)
static constexpr int SM_X0E  = 16384;    // 4096 x float2 (x0 epilogue pairs)
static constexpr int SM_WB   = 49152;    // 8 warps x 1152 floats (16 l x 72)
static constexpr int SM_RAW  = SM_WB;    // 32KB staging overlay (pre-mainloop)
static constexpr int WB_WARP = 1152;     // floats per warp chunk buffer
static constexpr int SMEM_TOTAL = SM_WB + 8 * WB_WARP * 4;   // 86016 (84KB)

__global__ __launch_bounds__(256, 2) void fm_main_kernel(
    const float* __restrict__ x0g,
    const float* __restrict__ x1g,
    float* __restrict__ outg)
{
    extern __shared__ __align__(16) unsigned char smem[];
    uint2*  x1B  = (uint2*)(smem + SM_X1B);
    float2* x0e  = (float2*)(smem + SM_X0E);
    float*  wb   = (float*)(smem + SM_WB);
    float4* raw4 = (float4*)(smem + SM_RAW);
    float*  raw  = (float*)(smem + SM_RAW);

    int tid = threadIdx.x;
    int w = tid >> 5, lane = tid & 31;
    int gid = lane >> 2, q = lane & 3;
    int bbase = blockIdx.x * 8;   // 8 b's -> 128 (b,d) rows per CTA

    // ---- stage x1 slab (8 b x 64 j x 16 d) coalesced, then build B frags ----
    const float4* x1s = (const float4*)(x1g + (size_t)bbase * 1024);
    for (int e = tid; e < 2048; e += 256) raw4[e] = x1s[e];
    __syncthreads();
    // B fragment (mc, t, lane): {x1[r][k0], [k0+1], [k0+8], [k0+9]},
    // r = mc*8 + gid (the n8 dim = m rows), k0 = 16t + 2q.
    for (int e = tid; e < 2048; e += 256) {
        int mc = e >> 7, t = (e >> 5) & 3, ln = e & 31;
        int g2 = ln >> 2, q2 = ln & 3;
        int r = mc * 8 + g2;
        int bl = r >> 4, d = r & 15;
        int k0 = t * 16 + q2 * 2;
        const float* base = raw + bl * 1024 + d;
        float f0 = base[k0 * 16];
        float f1 = base[(k0 + 1) * 16];
        float f2 = base[(k0 + 8) * 16];
        float f3 = base[(k0 + 9) * 16];
        x1B[e] = make_uint2(pack_half2(f0, f1), pack_half2(f2, f3));
    }
    __syncthreads();

    // ---- stage x0 slab, build epilogue pairs x0e[i*64 + mc*4 + q] ----
    const float4* x0s = (const float4*)(x0g + (size_t)bbase * 1024);
    for (int e = tid; e < 2048; e += 256) raw4[e] = x0s[e];
    __syncthreads();
    for (int e = tid; e < 4096; e += 256) {
        int i = e >> 6, mc = (e >> 2) & 15, q2 = e & 3;
        int m0 = mc * 8 + q2 * 2;
        int bl = m0 >> 4, d = m0 & 15;     // m0 even -> m0+1 same b
        const float* base = raw + bl * 1024 + i * 16 + d;
        x0e[e] = make_float2(base[0], base[1]);
    }
    __syncthreads();

    // ---- main loop: 4 passes; warp w handles i0 = 16g+w, i1 = 16g+8+w ----
    float acc[16][4];
    #pragma unroll
    for (int mc = 0; mc < 16; ++mc)
        #pragma unroll
        for (int j = 0; j < 4; ++j) acc[mc][j] = 0.0f;

    for (int g = 0; g < 4; ++g) {
        int i0 = g * 16 + w;
        int i1 = i0 + 8;
        uint4 a0[4], a1[4];
        #pragma unroll
        for (int t = 0; t < 4; ++t) {
            a0[t] = g_Wfrag[(i0 * 4 + t) * 32 + lane];
            a1[t] = g_Wfrag[(i1 * 4 + t) * 32 + lane];
        }
        const float2* p0 = x0e + i0 * 64 + q;
        const float2* p1 = x0e + i1 * 64 + q;

        #pragma unroll
        for (int mc = 0; mc < 16; ++mc) {
            uint2 b0 = x1B[(mc * 4 + 0) * 32 + lane];
            uint2 b1 = x1B[(mc * 4 + 1) * 32 + lane];
            uint2 b2 = x1B[(mc * 4 + 2) * 32 + lane];
            uint2 b3 = x1B[(mc * 4 + 3) * 32 + lane];
            float2 xv0 = p0[mc * 4];
            float2 xv1 = p1[mc * 4];

            // i0: two independent depth-2 chains
            float ch[4] = {0.f, 0.f, 0.f, 0.f};
            float cl[4] = {0.f, 0.f, 0.f, 0.f};
            mma16816(ch, a0[0], b0);
            mma16816(cl, a0[2], b2);
            mma16816(ch, a0[1], b1);
            mma16816(cl, a0[3], b3);
            // i1: two more independent chains
            float dh[4] = {0.f, 0.f, 0.f, 0.f};
            float dl[4] = {0.f, 0.f, 0.f, 0.f};
            mma16816(dh, a1[0], b0);
            mma16816(dl, a1[2], b2);
            mma16816(dh, a1[1], b1);
            mma16816(dl, a1[3], b3);

            // c0,c1: l=gid, m = mc*8+2q, +1 ; c2,c3: l=gid+8, same m.
            acc[mc][0] = fmaf(xv1.x, dh[0] + dl[0], fmaf(xv0.x, ch[0] + cl[0], acc[mc][0]));
            acc[mc][1] = fmaf(xv1.y, dh[1] + dl[1], fmaf(xv0.y, ch[1] + cl[1], acc[mc][1]));
            acc[mc][2] = fmaf(xv1.x, dh[2] + dl[2], fmaf(xv0.x, ch[2] + cl[2], acc[mc][2]));
            acc[mc][3] = fmaf(xv1.y, dh[3] + dl[3], fmaf(xv0.y, ch[3] + cl[3], acc[mc][3]));
        }
    }

    // ---- cross-warp reduction over i-partials, two mc-chunks of 8 ----
    #pragma unroll
    for (int chunk = 0; chunk < 2; ++chunk) {
        float* wbw = wb + w * WB_WARP;
        #pragma unroll
        for (int mcl = 0; mcl < 8; ++mcl) {
            int mc = chunk * 8 + mcl;
            int m0 = mcl * 8 + q * 2;           // local m in [0,64)
            *(float2*)&wbw[gid * 72 + m0]       = make_float2(acc[mc][0], acc[mc][1]);
            *(float2*)&wbw[(gid + 8) * 72 + m0] = make_float2(acc[mc][2], acc[mc][3]);
        }
        __syncthreads();

        for (int o = tid; o < 1024; o += 256) {
            int l = o >> 6, lm = o & 63;        // local m
            float s = 0.0f;
            #pragma unroll
            for (int ww = 0; ww < 8; ++ww)
                s += wb[ww * WB_WARP + l * 72 + lm];
            int m = chunk * 64 + lm;
            int bl = m >> 4, d = m & 15;
            outg[(size_t)(bbase + bl) * 256 + l * 16 + d] = s;
        }
        __syncthreads();
    }
}

// ------------------------------------------------------------------ launch --
extern "C" void kernel_launch(void* const* d_in, const int* in_sizes, int n_in,
                              void* d_out, int out_size) {
    const float* x0 = (const float*)d_in[0];
    const float* x1 = (const float*)d_in[1];
    const float* filters = (const float*)d_in[2];
    float* out = (float*)d_out;

    cudaFuncSetAttribute(fm_main_kernel,
                         cudaFuncAttributeMaxDynamicSharedMemorySize, SMEM_TOTAL);

    prep_w_kernel<<<32, 256>>>(filters);
    fm_main_kernel<<<256, 256, SMEM_TOTAL>>>(x0, x1, out);
}

// round 7
// speedup vs baseline: 1.0673x; 1.0673x over previous
#include <cuda_runtime.h>
#include <cuda_fp16.h>
#include <cstdint>

// ============================================================================
// out[b,l,d] = sum_{i,j} x0[b,i,d]*x1[b,j,d]*filters[i*64+j, l]
// B=2048, F1=F2=64, D=16, L=16.
//
// R7: feeding-bound fix. Warp = (i-half h, mc-quarter Q).
//  - B fragments (x1) register-resident for the whole mainloop (32 regs).
//  - x0 folded into B per i via mul.f16x2 -> HMMA accumulates over ALL i,k
//    in fp32 C fragments (4 independent 128-long chains per warp).
//  - W streamed LDG.128 (L1-resident image), prefetch 1 i ahead.
//  - No LDS on any MMA operand path; tiny 2-way cross-warp reduce at end.
// ============================================================================

// Pre-arranged W fragment image: [i(64)][kstep(4)][lane(32)] x 16B.
__device__ __align__(16) uint4 g_Wfrag[64 * 4 * 32];

__device__ __forceinline__ uint32_t pack_half2(float a, float b) {
    __half2 h = __floats2half2_rn(a, b);   // .x (low 16b) = a, .y = b
    return *(uint32_t*)&h;
}

__device__ __forceinline__ uint32_t hmul2(uint32_t a, uint32_t b) {
    uint32_t d;
    asm("mul.rn.f16x2 %0, %1, %2;" : "=r"(d) : "r"(a), "r"(b));
    return d;
}

__device__ __forceinline__ void mma16816(float c[4], const uint4& a, const uint2& b) {
    asm volatile(
        "mma.sync.aligned.m16n8k16.row.col.f32.f16.f16.f32 "
        "{%0,%1,%2,%3}, {%4,%5,%6,%7}, {%8,%9}, {%0,%1,%2,%3};\n"
        : "+f"(c[0]), "+f"(c[1]), "+f"(c[2]), "+f"(c[3])
        : "r"(a.x), "r"(a.y), "r"(a.z), "r"(a.w), "r"(b.x), "r"(b.y));
}

// ---------------------------------------------------------- prep kernel -----
// A-fragment mapping (m16k16, row-major), lane = 4*gid + q:
//   reg0 = {A[gid][2q],   A[gid][2q+1]}    reg1 = {A[gid+8][2q],   A[gid+8][2q+1]}
//   reg2 = {A[gid][2q+8], A[gid][2q+9]}    reg3 = {A[gid+8][2q+8], A[gid+8][2q+9]}
// A row = l; A col = k = j (global j = 16*kstep + local).
__global__ void prep_w_kernel(const float* __restrict__ filters) {
    int idx  = blockIdx.x * 256 + threadIdx.x;    // 8192 total
    int i    = (idx >> 7) & 63;
    int t    = (idx >> 5) & 3;
    int lane = idx & 31;
    int gid = lane >> 2, q = lane & 3;
    int k0 = t * 16 + q * 2;
    int l0 = gid, l1 = gid + 8;

    float e[8];
    int ls[8] = {l0, l0, l1, l1, l0, l0, l1, l1};
    int ks[8] = {k0, k0 + 1, k0, k0 + 1, k0 + 8, k0 + 9, k0 + 8, k0 + 9};
    #pragma unroll
    for (int j = 0; j < 8; ++j)
        e[j] = filters[(i * 64 + ks[j]) * 16 + ls[j]];

    g_Wfrag[idx] = make_uint4(pack_half2(e[0], e[1]), pack_half2(e[2], e[3]),
                              pack_half2(e[4], e[5]), pack_half2(e[6], e[7]));
}

// ------------------------------------------------------------ main kernel ---
// SMEM: x0h (32KB, persists) | raw staging 32KB (becomes wb after mainloop)
static constexpr int SM_X0H = 0;        // 8192 u32: dup-h2(x0[m,i]) at [i*128+m]
static constexpr int SM_RAW = 32768;    // 8192 f32 staging; wb overlay later
static constexpr int SMEM_TOTAL = 65536;

__global__ __launch_bounds__(256, 2) void fm_main_kernel(
    const float* __restrict__ x0g,
    const float* __restrict__ x1g,
    float* __restrict__ outg)
{
    extern __shared__ __align__(16) unsigned char smem[];
    uint32_t* x0h = (uint32_t*)(smem + SM_X0H);
    float*    raw = (float*)(smem + SM_RAW);
    float4*   raw4 = (float4*)(smem + SM_RAW);
    float*    wb  = (float*)(smem + SM_RAW);   // after mainloop

    int tid = threadIdx.x;
    int w = tid >> 5, lane = tid & 31;
    int gid = lane >> 2, q = lane & 3;
    int Q = w & 3;         // mc-quarter: mc = Q*4 + mcl
    int h = w >> 2;        // i-half: i = h*32 + il
    int bbase = blockIdx.x * 8;   // 8 b's -> 128 (b,d) rows per CTA

    // ---- stage x1 slab coalesced, then build register-resident B frags ----
    const float4* x1s = (const float4*)(x1g + (size_t)bbase * 1024);
    for (int e = tid; e < 2048; e += 256) raw4[e] = x1s[e];
    __syncthreads();

    // B fragment (mcl, t): lane holds {x1[r][k0], [k0+1], [k0+8], [k0+9]},
    // r = (Q*4+mcl)*8 + gid (the n8 dim = m rows), k0 = 16t + 2q.
    uint2 Bf[4][4];
    #pragma unroll
    for (int mcl = 0; mcl < 4; ++mcl) {
        int r = (Q * 4 + mcl) * 8 + gid;
        int bl = r >> 4, d = r & 15;
        const float* base = raw + bl * 1024 + d;
        #pragma unroll
        for (int t = 0; t < 4; ++t) {
            int k0 = t * 16 + q * 2;
            float f0 = base[k0 * 16];
            float f1 = base[(k0 + 1) * 16];
            float f2 = base[(k0 + 8) * 16];
            float f3 = base[(k0 + 9) * 16];
            Bf[mcl][t] = make_uint2(pack_half2(f0, f1), pack_half2(f2, f3));
        }
    }
    __syncthreads();

    // ---- stage x0 slab, build x0h[i*128 + m] = {h,h} with h=fp16(x0[m,i]) ----
    const float4* x0s = (const float4*)(x0g + (size_t)bbase * 1024);
    for (int e = tid; e < 2048; e += 256) raw4[e] = x0s[e];
    __syncthreads();
    for (int e = tid; e < 8192; e += 256) {
        int i = e >> 7, m = e & 127;
        int bl = m >> 4, d = m & 15;
        float v = raw[bl * 1024 + i * 16 + d];
        __half hh = __float2half(v);
        x0h[e] = (uint32_t)*(unsigned short*)&hh * 0x00010001u;
    }
    __syncthreads();

    // ---- mainloop: 32 i's; acc = fp32 HMMA C frags, chained over all i,k ----
    float acc[4][4];
    #pragma unroll
    for (int mcl = 0; mcl < 4; ++mcl)
        #pragma unroll
        for (int r = 0; r < 4; ++r) acc[mcl][r] = 0.0f;

    const uint4* wp = g_Wfrag + lane;
    int i0 = h * 32;
    uint4 Wc[4], Wn[4];
    #pragma unroll
    for (int t = 0; t < 4; ++t) Wc[t] = wp[(i0 * 4 + t) * 32];

    for (int il = 0; il < 32; ++il) {
        int i = i0 + il;
        if (il < 31) {
            #pragma unroll
            for (int t = 0; t < 4; ++t) Wn[t] = wp[((i + 1) * 4 + t) * 32];
        }
        #pragma unroll
        for (int mcl = 0; mcl < 4; ++mcl) {
            uint32_t xh = x0h[i * 128 + (Q * 4 + mcl) * 8 + gid];  // broadcast
            #pragma unroll
            for (int t = 0; t < 4; ++t) {
                uint2 bs = make_uint2(hmul2(Bf[mcl][t].x, xh),
                                      hmul2(Bf[mcl][t].y, xh));
                mma16816(acc[mcl], Wc[t], bs);
            }
        }
        #pragma unroll
        for (int t = 0; t < 4; ++t) Wc[t] = Wn[t];
    }

    // ---- partial writeback: wb[(w*4+mcl)*136 + l*8 + mloc] (pad kills conflicts)
    #pragma unroll
    for (int mcl = 0; mcl < 4; ++mcl) {
        float* bptr = wb + (w * 4 + mcl) * 136;
        *(float2*)&bptr[gid * 8 + 2 * q]       = make_float2(acc[mcl][0], acc[mcl][1]);
        *(float2*)&bptr[(gid + 8) * 8 + 2 * q] = make_float2(acc[mcl][2], acc[mcl][3]);
    }
    __syncthreads();

    // ---- 2-way reduce (i-halves) + coalesced store ----
    for (int o = tid; o < 2048; o += 256) {
        int l = o >> 7, m = o & 127;
        int Q2 = m >> 5, mcl = (m >> 3) & 3, mloc = m & 7;
        int off = (Q2 * 4 + mcl) * 136 + l * 8 + mloc;
        float s = wb[off] + wb[off + 16 * 136];   // partner warp w+4
        int bl = m >> 4, d = m & 15;
        outg[(size_t)(bbase + bl) * 256 + l * 16 + d] = s;
    }
}

// ------------------------------------------------------------------ launch --
extern "C" void kernel_launch(void* const* d_in, const int* in_sizes, int n_in,
                              void* d_out, int out_size) {
    const float* x0 = (const float*)d_in[0];
    const float* x1 = (const float*)d_in[1];
    const float* filters = (const float*)d_in[2];
    float* out = (float*)d_out;

    cudaFuncSetAttribute(fm_main_kernel,
                         cudaFuncAttributeMaxDynamicSharedMemorySize, SMEM_TOTAL);

    prep_w_kernel<<<32, 256>>>(filters);
    fm_main_kernel<<<256, 256, SMEM_TOTAL>>>(x0, x1, out);
}